// round 2
// baseline (speedup 1.0000x reference)
#include <cuda_runtime.h>

#define D      512
#define DD     (D * D)
#define TILE   64
#define KI     16
#define NSITES 62

// Scratch (device globals: allocation-free).
// acc is maintained as two partial buffers: acc = part0 + part1
// (phase2 writes one partial per s, avoiding atomics / extra reduction kernel).
__device__ __align__(16) float g_accr[2][DD];
__device__ __align__(16) float g_acci[2][DD];
// T tensors, stored TRANSPOSED: Tt[s][j][k] = T[s,k,j]
__device__ __align__(16) float g_Ttr[2][DD];
__device__ __align__(16) float g_Tti[2][DD];

// ---------------------------------------------------------------------------
// init: cont0[j,k] = sum_s left[s,0,j] * conj(left[s,0,k])
// ---------------------------------------------------------------------------
__global__ void init_kernel(const float* __restrict__ lr,
                            const float* __restrict__ li) {
    int idx = blockIdx.x * blockDim.x + threadIdx.x;
    if (idx >= DD) return;
    int j = idx >> 9;
    int k = idx & (D - 1);
    float ar = 0.f, ai = 0.f;
#pragma unroll
    for (int s = 0; s < 2; ++s) {
        float lrj = lr[s * D + j], lij = li[s * D + j];
        float lrk = lr[s * D + k], lik = li[s * D + k];
        ar += lrj * lrk + lij * lik;        // Re(l_j * conj(l_k))
        ai += lij * lrk - lrj * lik;        // Im(l_j * conj(l_k))
    }
    g_accr[0][idx] = ar;
    g_acci[0][idx] = ai;
    g_accr[1][idx] = 0.f;
    g_acci[1][idx] = 0.f;
}

// ---------------------------------------------------------------------------
// phase1: T[s,k,j] = sum_i A[s,i,k] * acc[i,j]          (complex, no conj)
// Both operands have reduction index i as the ROW -> coalesced tile loads.
// Output stored transposed: Tt[s][j][k], so phase2 has the same TN shape.
// ---------------------------------------------------------------------------
__global__ __launch_bounds__(256, 2)
void phase1_kernel(const float* __restrict__ Ar_base,
                   const float* __restrict__ Ai_base) {
    const int s = blockIdx.z;
    const float* __restrict__ Ar = Ar_base + (size_t)s * DD;
    const float* __restrict__ Ai = Ai_base + (size_t)s * DD;
    const int k0 = blockIdx.y * TILE;
    const int j0 = blockIdx.x * TILE;

    __shared__ __align__(16) float sAr[KI][TILE], sAi[KI][TILE];
    __shared__ __align__(16) float sBr[KI][TILE], sBi[KI][TILE];

    const int t    = threadIdx.x;
    const int lrow = t >> 4;           // 0..15 : load row within KI
    const int lcol = (t & 15) << 2;    // 0..60 : load col (float4)
    const int ty   = t >> 4;           // k-group
    const int tx   = t & 15;           // j-group

    float cr[4][4] = {}, ci[4][4] = {};

    for (int i0 = 0; i0 < D; i0 += KI) {
        const int arow = (i0 + lrow) * D;
        // gmem loads into registers (overlap with previous compute)
        float4 va_r = *(const float4*)(Ar + arow + k0 + lcol);
        float4 va_i = *(const float4*)(Ai + arow + k0 + lcol);
        float4 b0r  = *(const float4*)(g_accr[0] + arow + j0 + lcol);
        float4 b1r  = *(const float4*)(g_accr[1] + arow + j0 + lcol);
        float4 b0i  = *(const float4*)(g_acci[0] + arow + j0 + lcol);
        float4 b1i  = *(const float4*)(g_acci[1] + arow + j0 + lcol);
        float4 vb_r = make_float4(b0r.x + b1r.x, b0r.y + b1r.y,
                                  b0r.z + b1r.z, b0r.w + b1r.w);
        float4 vb_i = make_float4(b0i.x + b1i.x, b0i.y + b1i.y,
                                  b0i.z + b1i.z, b0i.w + b1i.w);

        __syncthreads();
        *(float4*)&sAr[lrow][lcol] = va_r;
        *(float4*)&sAi[lrow][lcol] = va_i;
        *(float4*)&sBr[lrow][lcol] = vb_r;
        *(float4*)&sBi[lrow][lcol] = vb_i;
        __syncthreads();

#pragma unroll
        for (int i = 0; i < KI; ++i) {
            float4 f;
            float arv[4], aiv[4], brv[4], biv[4];
            f = *(const float4*)&sAr[i][ty << 2]; arv[0]=f.x; arv[1]=f.y; arv[2]=f.z; arv[3]=f.w;
            f = *(const float4*)&sAi[i][ty << 2]; aiv[0]=f.x; aiv[1]=f.y; aiv[2]=f.z; aiv[3]=f.w;
            f = *(const float4*)&sBr[i][tx << 2]; brv[0]=f.x; brv[1]=f.y; brv[2]=f.z; brv[3]=f.w;
            f = *(const float4*)&sBi[i][tx << 2]; biv[0]=f.x; biv[1]=f.y; biv[2]=f.z; biv[3]=f.w;
#pragma unroll
            for (int kk = 0; kk < 4; ++kk)
#pragma unroll
                for (int jj = 0; jj < 4; ++jj) {
                    cr[kk][jj] = fmaf(arv[kk], brv[jj], cr[kk][jj]);
                    cr[kk][jj] = fmaf(-aiv[kk], biv[jj], cr[kk][jj]);
                    ci[kk][jj] = fmaf(arv[kk], biv[jj], ci[kk][jj]);
                    ci[kk][jj] = fmaf(aiv[kk], brv[jj], ci[kk][jj]);
                }
        }
    }

    // store transposed: Tt[j][k]
    float* __restrict__ Tr = g_Ttr[s];
    float* __restrict__ Ti = g_Tti[s];
#pragma unroll
    for (int jj = 0; jj < 4; ++jj) {
        int j = j0 + (tx << 2) + jj;
        size_t off = (size_t)j * D + k0 + (ty << 2);
        *(float4*)(Tr + off) = make_float4(cr[0][jj], cr[1][jj], cr[2][jj], cr[3][jj]);
        *(float4*)(Ti + off) = make_float4(ci[0][jj], ci[1][jj], ci[2][jj], ci[3][jj]);
    }
}

// ---------------------------------------------------------------------------
// phase2: acc_part[s][k,l] = sum_j Tt[s][j,k] * conj(A[s,j,l])
// (downstream consumers read acc = part0 + part1)
// ---------------------------------------------------------------------------
__global__ __launch_bounds__(256, 2)
void phase2_kernel(const float* __restrict__ Ar_base,
                   const float* __restrict__ Ai_base) {
    const int s = blockIdx.z;
    const float* __restrict__ Xr = g_Ttr[s];
    const float* __restrict__ Xi = g_Tti[s];
    const float* __restrict__ Yr = Ar_base + (size_t)s * DD;
    const float* __restrict__ Yi = Ai_base + (size_t)s * DD;
    const int k0 = blockIdx.y * TILE;
    const int l0 = blockIdx.x * TILE;

    __shared__ __align__(16) float sXr[KI][TILE], sXi[KI][TILE];
    __shared__ __align__(16) float sYr[KI][TILE], sYi[KI][TILE];

    const int t    = threadIdx.x;
    const int lrow = t >> 4;
    const int lcol = (t & 15) << 2;
    const int ty   = t >> 4;           // k-group
    const int tx   = t & 15;           // l-group

    float cr[4][4] = {}, ci[4][4] = {};

    for (int j0i = 0; j0i < D; j0i += KI) {
        const int jrow = (j0i + lrow) * D;
        float4 vx_r = *(const float4*)(Xr + jrow + k0 + lcol);
        float4 vx_i = *(const float4*)(Xi + jrow + k0 + lcol);
        float4 vy_r = *(const float4*)(Yr + jrow + l0 + lcol);
        float4 vy_i = *(const float4*)(Yi + jrow + l0 + lcol);

        __syncthreads();
        *(float4*)&sXr[lrow][lcol] = vx_r;
        *(float4*)&sXi[lrow][lcol] = vx_i;
        *(float4*)&sYr[lrow][lcol] = vy_r;
        *(float4*)&sYi[lrow][lcol] = vy_i;
        __syncthreads();

#pragma unroll
        for (int i = 0; i < KI; ++i) {
            float4 f;
            float xrv[4], xiv[4], yrv[4], yiv[4];
            f = *(const float4*)&sXr[i][ty << 2]; xrv[0]=f.x; xrv[1]=f.y; xrv[2]=f.z; xrv[3]=f.w;
            f = *(const float4*)&sXi[i][ty << 2]; xiv[0]=f.x; xiv[1]=f.y; xiv[2]=f.z; xiv[3]=f.w;
            f = *(const float4*)&sYr[i][tx << 2]; yrv[0]=f.x; yrv[1]=f.y; yrv[2]=f.z; yrv[3]=f.w;
            f = *(const float4*)&sYi[i][tx << 2]; yiv[0]=f.x; yiv[1]=f.y; yiv[2]=f.z; yiv[3]=f.w;
#pragma unroll
            for (int kk = 0; kk < 4; ++kk)
#pragma unroll
                for (int ll = 0; ll < 4; ++ll) {
                    // X * conj(Y)
                    cr[kk][ll] = fmaf(xrv[kk], yrv[ll], cr[kk][ll]);
                    cr[kk][ll] = fmaf(xiv[kk], yiv[ll], cr[kk][ll]);
                    ci[kk][ll] = fmaf(xiv[kk], yrv[ll], ci[kk][ll]);
                    ci[kk][ll] = fmaf(-xrv[kk], yiv[ll], ci[kk][ll]);
                }
        }
    }

    float* __restrict__ Cr = g_accr[s];
    float* __restrict__ Ci = g_acci[s];
#pragma unroll
    for (int kk = 0; kk < 4; ++kk) {
        int k = k0 + (ty << 2) + kk;
        size_t off = (size_t)k * D + l0 + (tx << 2);
        *(float4*)(Cr + off) = make_float4(cr[kk][0], cr[kk][1], cr[kk][2], cr[kk][3]);
        *(float4*)(Ci + off) = make_float4(ci[kk][0], ci[kk][1], ci[kk][2], ci[kk][3]);
    }
}

// ---------------------------------------------------------------------------
// final: out = Re( sum_s sum_{i,j} right[s,i] * acc[i,j] * conj(right[s,j]) )
// ---------------------------------------------------------------------------
__global__ void final_kernel(const float* __restrict__ rr,
                             const float* __restrict__ ri,
                             float* __restrict__ out) {
    const int j = threadIdx.x;   // 0..511
    float res = 0.f;
#pragma unroll
    for (int s = 0; s < 2; ++s) {
        float wr = 0.f, wi = 0.f;
        for (int i = 0; i < D; ++i) {
            float ar = g_accr[0][i * D + j] + g_accr[1][i * D + j];
            float ai = g_acci[0][i * D + j] + g_acci[1][i * D + j];
            float xr = rr[s * D + i], xi = ri[s * D + i];
            wr += xr * ar - xi * ai;
            wi += xr * ai + xi * ar;
        }
        // Re( w_j * conj(r_j) )
        res += wr * rr[s * D + j] + wi * ri[s * D + j];
    }
    __shared__ float sd[D];
    sd[j] = res;
    __syncthreads();
    for (int st = D / 2; st > 0; st >>= 1) {
        if (j < st) sd[j] += sd[j + st];
        __syncthreads();
    }
    if (j == 0) out[0] = sd[0];
}

// ---------------------------------------------------------------------------
extern "C" void kernel_launch(void* const* d_in, const int* in_sizes, int n_in,
                              void* d_out, int out_size) {
    const float* left_r  = (const float*)d_in[0];
    const float* left_i  = (const float*)d_in[1];
    const float* bulk_r  = (const float*)d_in[2];
    const float* bulk_i  = (const float*)d_in[3];
    const float* right_r = (const float*)d_in[4];
    const float* right_i = (const float*)d_in[5];
    float* out = (float*)d_out;

    init_kernel<<<DD / 256, 256>>>(left_r, left_i);

    dim3 grid(D / TILE, D / TILE, 2);
    for (int site = 0; site < NSITES; ++site) {
        const float* Ar = bulk_r + (size_t)site * 2 * DD;
        const float* Ai = bulk_i + (size_t)site * 2 * DD;
        phase1_kernel<<<grid, 256>>>(Ar, Ai);
        phase2_kernel<<<grid, 256>>>(Ar, Ai);
    }

    final_kernel<<<1, D>>>(right_r, right_i, out);
}

// round 4
// speedup vs baseline: 1.9367x; 1.9367x over previous
#include <cuda_runtime.h>
#include <cuda_bf16.h>
#include <mma.h>
#include <cstdint>

using namespace nvcuda;

#define D       512
#define DD      (D * D)
#define NSITES  62
#define NMAT    (NSITES * 2)      // 124

#define KC      32                // K elems per chunk
#define LDS     40                // padded smem row (elems) -> 80B, conflict-free
#define XT_E    (128 * LDS)       // X tile elems
#define YT_E    (64 * LDS)
#define XTILE_B (XT_E * 2)        // 10240 B
#define YTILE_B (YT_E * 2)        // 5120 B
#define YOFF    (6 * XTILE_B)     // 61440
#define STAGE_B (6 * XTILE_B + 6 * YTILE_B)   // 92160
#define SMEMSZ  (2 * STAGE_B)                 // 184320

// ---------------------------------------------------------------------------
// Device scratch (static: allocation-free)
// variant order for AT: 0 rh,1 rl,2 ih,3 il,4 sh,5 sl (s=r+i),6 dh,7 dl (d=r-i)
// T variants (X-side): rh,rl,ih,il,sh,sl.  Q variants (Y-side): rh,rl,ih,il,dh,dl
// ---------------------------------------------------------------------------
__device__ __nv_bfloat16 g_ATv[NMAT][8][DD];          // ~496 MB
__device__ __nv_bfloat16 g_T[2][6][DD];
__device__ __nv_bfloat16 g_Q[6][DD];
__device__ float g_p1[2][2][2][DD];                   // [s][kpart][r/i]
__device__ float g_p2[4][2][DD];                      // [part][r/i]
__device__ float g_accr[DD], g_acci[DD];

// ---------------------------------------------------------------------------
__device__ __forceinline__ uint32_t smem_u32(const void* p) {
    uint32_t a;
    asm("{ .reg .u64 t; cvta.to.shared.u64 t, %1; cvt.u32.u64 %0, t; }"
        : "=r"(a) : "l"(p));
    return a;
}

__device__ __forceinline__ void cpa8(uint32_t dst, const __nv_bfloat16* src) {
    asm volatile("cp.async.ca.shared.global [%0], [%1], 8;"
                 :: "r"(dst), "l"(src));
}

__device__ __forceinline__ void split2(float v, __nv_bfloat16& h, __nv_bfloat16& l) {
    h = __float2bfloat16(v);
    l = __float2bfloat16(v - __bfloat162float(h));
}

// ---------------------------------------------------------------------------
// prep: AT[m][k][i] = bulk[m][i][k]; write 8 bf16 variants (r,i,sum,diff hi/lo)
// ---------------------------------------------------------------------------
__global__ void prep_kernel(const float* __restrict__ br,
                            const float* __restrict__ bi) {
    const int m  = blockIdx.z;
    const int i0 = blockIdx.y * 32;
    const int k0 = blockIdx.x * 32;
    const int tx = threadIdx.x, ty = threadIdx.y;

    __shared__ float tr[32][33], ti[32][33];
    const float* sr = br + (size_t)m * DD;
    const float* si = bi + (size_t)m * DD;
#pragma unroll
    for (int r = 0; r < 32; r += 8) {
        tr[ty + r][tx] = sr[(i0 + ty + r) * D + k0 + tx];
        ti[ty + r][tx] = si[(i0 + ty + r) * D + k0 + tx];
    }
    __syncthreads();
#pragma unroll
    for (int r = 0; r < 32; r += 8) {
        int out = (k0 + ty + r) * D + i0 + tx;
        float vr = tr[tx][ty + r], vi = ti[tx][ty + r];
        float vs = vr + vi, vd = vr - vi;
        __nv_bfloat16 h, l;
        split2(vr, h, l); g_ATv[m][0][out] = h; g_ATv[m][1][out] = l;
        split2(vi, h, l); g_ATv[m][2][out] = h; g_ATv[m][3][out] = l;
        split2(vs, h, l); g_ATv[m][4][out] = h; g_ATv[m][5][out] = l;
        split2(vd, h, l); g_ATv[m][6][out] = h; g_ATv[m][7][out] = l;
    }
}

// ---------------------------------------------------------------------------
// init: Q[j][k] = acc0[j,k] = sum_s l_sj conj(l_sk); write Y-side variants
// ---------------------------------------------------------------------------
__global__ void init_kernel(const float* __restrict__ lr,
                            const float* __restrict__ li) {
    int idx = blockIdx.x * 256 + threadIdx.x;
    int j = idx >> 9, k = idx & (D - 1);
    float ar = 0.f, ai = 0.f;
#pragma unroll
    for (int s = 0; s < 2; ++s) {
        float lrj = lr[s * D + j], lij = li[s * D + j];
        float lrk = lr[s * D + k], lik = li[s * D + k];
        ar += lrj * lrk + lij * lik;
        ai += lij * lrk - lrj * lik;
    }
    float ad = ar - ai;
    __nv_bfloat16 h, l;
    split2(ar, h, l); g_Q[0][idx] = h; g_Q[1][idx] = l;
    split2(ai, h, l); g_Q[2][idx] = h; g_Q[3][idx] = l;
    split2(ad, h, l); g_Q[4][idx] = h; g_Q[5][idx] = l;
}

// ---------------------------------------------------------------------------
// GEMM: C[m,n] = sum_K X[m,K] * conj(Y[n,K]), split-bf16 Karatsuba, split-K.
//  mode 0 (phase1): X = AT_(site,s), Y = Q.   bz = s*2 + kpart (K=i, 256/part)
//  mode 1 (phase2): X = T_s,         Y = AT.  bz = part (s=part>>1, j-half)
// Block tile 128x64, warp tile 32x32, 8 warps. fp32 partial outputs.
// ---------------------------------------------------------------------------
__global__ __launch_bounds__(256, 1)
void gemm_kernel(int site, int mode) {
    extern __shared__ char smem[];
    const int t = threadIdx.x, w = t >> 5;
    const int warp_m = w >> 1, warp_n = w & 1;
    const int n0 = blockIdx.x * 64, m0 = blockIdx.y * 128;
    const int bz = blockIdx.z;

    const __nv_bfloat16 *Xv[6], *Yv[6];
    float *outR, *outI;
    int kbase;
    if (mode == 0) {
        int s = bz >> 1, kp = bz & 1, mm = site * 2 + s;
#pragma unroll
        for (int v = 0; v < 6; ++v) { Xv[v] = g_ATv[mm][v]; Yv[v] = g_Q[v]; }
        kbase = kp * 256;
        outR = g_p1[s][kp][0]; outI = g_p1[s][kp][1];
    } else {
        int part = bz, s = part >> 1, mm = site * 2 + s;
#pragma unroll
        for (int v = 0; v < 6; ++v) Xv[v] = g_T[s][v];
        Yv[0] = g_ATv[mm][0]; Yv[1] = g_ATv[mm][1];
        Yv[2] = g_ATv[mm][2]; Yv[3] = g_ATv[mm][3];
        Yv[4] = g_ATv[mm][6]; Yv[5] = g_ATv[mm][7];
        kbase = (part & 1) * 256;
        outR = g_p2[part][0]; outI = g_p2[part][1];
    }

    const uint32_t sb = smem_u32(smem);
    int xsrc[4], xdst[4], ysrc[2], ydst[2];
#pragma unroll
    for (int q = 0; q < 4; ++q) {
        int rs = t + q * 256, row = rs >> 3, seg = rs & 7;
        xsrc[q] = (m0 + row) * D + seg * 4;
        xdst[q] = row * (LDS * 2) + seg * 8;
    }
#pragma unroll
    for (int q = 0; q < 2; ++q) {
        int rs = t + q * 256, row = rs >> 3, seg = rs & 7;
        ysrc[q] = (n0 + row) * D + seg * 4;
        ydst[q] = row * (LDS * 2) + seg * 8;
    }

    auto prefetch = [&](int c, int buf) {
        const int koff = kbase + c * KC;
        const uint32_t base = sb + buf * STAGE_B;
#pragma unroll
        for (int v = 0; v < 6; ++v)
#pragma unroll
            for (int q = 0; q < 4; ++q)
                cpa8(base + v * XTILE_B + xdst[q], Xv[v] + xsrc[q] + koff);
#pragma unroll
        for (int v = 0; v < 6; ++v)
#pragma unroll
            for (int q = 0; q < 2; ++q)
                cpa8(base + YOFF + v * YTILE_B + ydst[q], Yv[v] + ysrc[q] + koff);
        asm volatile("cp.async.commit_group;");
    };

    wmma::fragment<wmma::accumulator, 16, 16, 16, float> p[3][2][2];
#pragma unroll
    for (int pr = 0; pr < 3; ++pr)
#pragma unroll
        for (int a = 0; a < 2; ++a)
#pragma unroll
            for (int b = 0; b < 2; ++b)
                wmma::fill_fragment(p[pr][a][b], 0.0f);

    prefetch(0, 0);

    for (int c = 0; c < 8; ++c) {
        const int buf = c & 1;
        if (c < 7) {
            prefetch(c + 1, buf ^ 1);
            asm volatile("cp.async.wait_group 1;");
        } else {
            asm volatile("cp.async.wait_group 0;");
        }
        __syncthreads();

        const __nv_bfloat16* xb = (const __nv_bfloat16*)(smem + buf * STAGE_B);
        const __nv_bfloat16* yb = (const __nv_bfloat16*)(smem + buf * STAGE_B + YOFF);
#pragma unroll
        for (int kk = 0; kk < 2; ++kk) {
#pragma unroll
            for (int pr = 0; pr < 3; ++pr) {
                wmma::fragment<wmma::matrix_a, 16, 16, 16, __nv_bfloat16, wmma::row_major> aH[2], aL[2];
                wmma::fragment<wmma::matrix_b, 16, 16, 16, __nv_bfloat16, wmma::col_major> bH[2], bL[2];
                const __nv_bfloat16* xh = xb + (2 * pr)     * XT_E + (warp_m * 32) * LDS + kk * 16;
                const __nv_bfloat16* xl = xb + (2 * pr + 1) * XT_E + (warp_m * 32) * LDS + kk * 16;
                const __nv_bfloat16* yh = yb + (2 * pr)     * YT_E + (warp_n * 32) * LDS + kk * 16;
                const __nv_bfloat16* yl = yb + (2 * pr + 1) * YT_E + (warp_n * 32) * LDS + kk * 16;
                wmma::load_matrix_sync(aH[0], xh,            LDS);
                wmma::load_matrix_sync(aH[1], xh + 16 * LDS, LDS);
                wmma::load_matrix_sync(aL[0], xl,            LDS);
                wmma::load_matrix_sync(aL[1], xl + 16 * LDS, LDS);
                wmma::load_matrix_sync(bH[0], yh,            LDS);
                wmma::load_matrix_sync(bH[1], yh + 16 * LDS, LDS);
                wmma::load_matrix_sync(bL[0], yl,            LDS);
                wmma::load_matrix_sync(bL[1], yl + 16 * LDS, LDS);
#pragma unroll
                for (int fm = 0; fm < 2; ++fm)
#pragma unroll
                    for (int fn = 0; fn < 2; ++fn) {
                        wmma::mma_sync(p[pr][fm][fn], aH[fm], bH[fn], p[pr][fm][fn]);
                        wmma::mma_sync(p[pr][fm][fn], aH[fm], bL[fn], p[pr][fm][fn]);
                        wmma::mma_sync(p[pr][fm][fn], aL[fm], bH[fn], p[pr][fm][fn]);
                    }
            }
        }
        __syncthreads();
    }

    // epilogue: Cr = P1 + P2 ; Ci = P3 - P1 + P2
    const size_t ob = (size_t)(m0 + warp_m * 32) * D + n0 + warp_n * 32;
    wmma::fragment<wmma::accumulator, 16, 16, 16, float> cf;
#pragma unroll
    for (int fm = 0; fm < 2; ++fm)
#pragma unroll
        for (int fn = 0; fn < 2; ++fn) {
            const size_t o = ob + fm * 16 * D + fn * 16;
#pragma unroll
            for (int e = 0; e < cf.num_elements; ++e)
                cf.x[e] = p[0][fm][fn].x[e] + p[1][fm][fn].x[e];
            wmma::store_matrix_sync(outR + o, cf, D, wmma::mem_row_major);
#pragma unroll
            for (int e = 0; e < cf.num_elements; ++e)
                cf.x[e] = p[2][fm][fn].x[e] - p[0][fm][fn].x[e] + p[1][fm][fn].x[e];
            wmma::store_matrix_sync(outI + o, cf, D, wmma::mem_row_major);
        }
}

// ---------------------------------------------------------------------------
// combine1: T_s = sum of 2 K-parts; emit X-side variants (r,i,sum) hi/lo
// ---------------------------------------------------------------------------
__global__ void combine1_kernel() {
    const int idx = blockIdx.x * 256 + threadIdx.x;
    const int s = blockIdx.y;
    float vr = g_p1[s][0][0][idx] + g_p1[s][1][0][idx];
    float vi = g_p1[s][0][1][idx] + g_p1[s][1][1][idx];
    float vs = vr + vi;
    __nv_bfloat16 h, l;
    split2(vr, h, l); g_T[s][0][idx] = h; g_T[s][1][idx] = l;
    split2(vi, h, l); g_T[s][2][idx] = h; g_T[s][3][idx] = l;
    split2(vs, h, l); g_T[s][4][idx] = h; g_T[s][5][idx] = l;
}

// ---------------------------------------------------------------------------
// combine2: acc = sum of 4 K-parts; emit fp32 acc + Y-side variants (r,i,diff)
// ---------------------------------------------------------------------------
__global__ void combine2_kernel() {
    const int idx = blockIdx.x * 256 + threadIdx.x;
    float vr = g_p2[0][0][idx] + g_p2[1][0][idx] + g_p2[2][0][idx] + g_p2[3][0][idx];
    float vi = g_p2[0][1][idx] + g_p2[1][1][idx] + g_p2[2][1][idx] + g_p2[3][1][idx];
    g_accr[idx] = vr;
    g_acci[idx] = vi;
    float vd = vr - vi;
    __nv_bfloat16 h, l;
    split2(vr, h, l); g_Q[0][idx] = h; g_Q[1][idx] = l;
    split2(vi, h, l); g_Q[2][idx] = h; g_Q[3][idx] = l;
    split2(vd, h, l); g_Q[4][idx] = h; g_Q[5][idx] = l;
}

// ---------------------------------------------------------------------------
// final: out = Re( sum_s r_s^T acc conj(r_s) )
// ---------------------------------------------------------------------------
__global__ void final_kernel(const float* __restrict__ rr,
                             const float* __restrict__ ri,
                             float* __restrict__ out) {
    const int j = threadIdx.x;
    float res = 0.f;
#pragma unroll
    for (int s = 0; s < 2; ++s) {
        float wr = 0.f, wi = 0.f;
        for (int i = 0; i < D; ++i) {
            float ar = g_accr[i * D + j];
            float ai = g_acci[i * D + j];
            float xr = rr[s * D + i], xi = ri[s * D + i];
            wr += xr * ar - xi * ai;
            wi += xr * ai + xi * ar;
        }
        res += wr * rr[s * D + j] + wi * ri[s * D + j];
    }
    __shared__ float sd[D];
    sd[j] = res;
    __syncthreads();
    for (int st = D / 2; st > 0; st >>= 1) {
        if (j < st) sd[j] += sd[j + st];
        __syncthreads();
    }
    if (j == 0) out[0] = sd[0];
}

// ---------------------------------------------------------------------------
extern "C" void kernel_launch(void* const* d_in, const int* in_sizes, int n_in,
                              void* d_out, int out_size) {
    const float* left_r  = (const float*)d_in[0];
    const float* left_i  = (const float*)d_in[1];
    const float* bulk_r  = (const float*)d_in[2];
    const float* bulk_i  = (const float*)d_in[3];
    const float* right_r = (const float*)d_in[4];
    const float* right_i = (const float*)d_in[5];
    float* out = (float*)d_out;

    cudaFuncSetAttribute(gemm_kernel,
                         cudaFuncAttributeMaxDynamicSharedMemorySize, SMEMSZ);

    prep_kernel<<<dim3(16, 16, NMAT), dim3(32, 8)>>>(bulk_r, bulk_i);
    init_kernel<<<DD / 256, 256>>>(left_r, left_i);

    for (int site = 0; site < NSITES; ++site) {
        gemm_kernel<<<dim3(8, 4, 4), 256, SMEMSZ>>>(site, 0);  // phase1 partials
        combine1_kernel<<<dim3(DD / 256, 2), 256>>>();          // -> T variants
        gemm_kernel<<<dim3(8, 4, 4), 256, SMEMSZ>>>(site, 1);  // phase2 partials
        combine2_kernel<<<DD / 256, 256>>>();                   // -> acc + Q
    }

    final_kernel<<<1, D>>>(right_r, right_i, out);
}